// round 1
// baseline (speedup 1.0000x reference)
#include <cuda_runtime.h>
#include <math.h>

// Problem constants
#define NB 2
#define NS 2048
#define ND 1024
#define NH 16
#define NDH 64
#define NF 4096
#define NM (NB*NS)          // 4096 rows total

// ---------------- scratch (device globals: allocation-free rule) ----------------
__device__ float g_h  [(size_t)NM*ND];          // LN output (reused for LN2)
__device__ float g_q  [(size_t)NM*ND];
__device__ float g_k  [(size_t)NM*ND];
__device__ float g_v  [(size_t)NM*ND];
__device__ float g_ctx[(size_t)NM*ND];
__device__ float g_ffn[(size_t)NM*NF];
__device__ float g_sc [(size_t)NB*NH*NS*NS];    // 537 MB score/attn buffer

// ---------------- LayerNorm: one block per row, 256 threads ----------------
__global__ void ln_kernel(const float* __restrict__ x,
                          const float* __restrict__ g,
                          const float* __restrict__ b,
                          float* __restrict__ out) {
    __shared__ float red[8];
    const int row = blockIdx.x;
    const int t = threadIdx.x;
    const float4 v = reinterpret_cast<const float4*>(x + (size_t)row * ND)[t];

    float s = v.x + v.y + v.z + v.w;
    #pragma unroll
    for (int o = 16; o; o >>= 1) s += __shfl_xor_sync(0xffffffffu, s, o);
    if ((t & 31) == 0) red[t >> 5] = s;
    __syncthreads();
    float tot = 0.f;
    #pragma unroll
    for (int i = 0; i < 8; i++) tot += red[i];
    const float mean = tot * (1.0f / ND);
    __syncthreads();

    const float dx = v.x - mean, dy = v.y - mean, dz = v.z - mean, dw = v.w - mean;
    float ss = dx*dx + dy*dy + dz*dz + dw*dw;
    #pragma unroll
    for (int o = 16; o; o >>= 1) ss += __shfl_xor_sync(0xffffffffu, ss, o);
    if ((t & 31) == 0) red[t >> 5] = ss;
    __syncthreads();
    float var = 0.f;
    #pragma unroll
    for (int i = 0; i < 8; i++) var += red[i];
    var *= (1.0f / ND);
    const float inv = rsqrtf(var + 1e-5f);

    const float4 gg = reinterpret_cast<const float4*>(g)[t];
    const float4 bb = reinterpret_cast<const float4*>(b)[t];
    float4 o4;
    o4.x = dx * inv * gg.x + bb.x;
    o4.y = dy * inv * gg.y + bb.y;
    o4.z = dz * inv * gg.z + bb.z;
    o4.w = dw * inv * gg.w + bb.w;
    reinterpret_cast<float4*>(out + (size_t)row * ND)[t] = o4;
}

// ---------------- General SGEMM: C = epi(A[M,K] @ W[K,N]) ----------------
// epilogue: v = acc + bias[n]; if(relu) v=max(v,0); v*=scale; if(res) v+=res[m,n]
// Requires M%128==0, N%128==0, K%16==0 (true for all uses here).
__global__ __launch_bounds__(256)
void sgemm_kernel(int M, int N, int K,
                  const float* __restrict__ A, const float* __restrict__ Bm,
                  const float* __restrict__ bias, const float* __restrict__ res,
                  float* __restrict__ C, float scale, int relu) {
    const int BM = 128, BN = 128, BK = 16;
    __shared__ float As[BK][BM];   // A stored transposed: As[k][m]
    __shared__ float Bs[BK][BN];

    const int bm = blockIdx.y * BM;
    const int bn = blockIdx.x * BN;
    const int tid = threadIdx.x;
    const int tx = tid & 15;   // 16 cols of threads
    const int ty = tid >> 4;   // 16 rows of threads

    float acc[8][8];
    #pragma unroll
    for (int i = 0; i < 8; i++)
        #pragma unroll
        for (int j = 0; j < 8; j++) acc[i][j] = 0.f;

    for (int k0 = 0; k0 < K; k0 += BK) {
        #pragma unroll
        for (int i = 0; i < 2; i++) {
            const int f = tid + i * 256;            // 512 float4 per tile
            const int ar = f >> 2, ac = (f & 3) << 2;
            const float4 a4 = *reinterpret_cast<const float4*>(
                &A[(size_t)(bm + ar) * K + k0 + ac]);
            As[ac + 0][ar] = a4.x;
            As[ac + 1][ar] = a4.y;
            As[ac + 2][ar] = a4.z;
            As[ac + 3][ar] = a4.w;
            const int br = f >> 5, bc = (f & 31) << 2;
            *reinterpret_cast<float4*>(&Bs[br][bc]) =
                *reinterpret_cast<const float4*>(&Bm[(size_t)(k0 + br) * N + bn + bc]);
        }
        __syncthreads();

        #pragma unroll
        for (int k = 0; k < BK; k++) {
            float ar[8], br[8];
            *reinterpret_cast<float4*>(&ar[0]) = *reinterpret_cast<const float4*>(&As[k][ty * 8]);
            *reinterpret_cast<float4*>(&ar[4]) = *reinterpret_cast<const float4*>(&As[k][ty * 8 + 4]);
            *reinterpret_cast<float4*>(&br[0]) = *reinterpret_cast<const float4*>(&Bs[k][tx * 8]);
            *reinterpret_cast<float4*>(&br[4]) = *reinterpret_cast<const float4*>(&Bs[k][tx * 8 + 4]);
            #pragma unroll
            for (int i = 0; i < 8; i++)
                #pragma unroll
                for (int j = 0; j < 8; j++)
                    acc[i][j] = fmaf(ar[i], br[j], acc[i][j]);
        }
        __syncthreads();
    }

    #pragma unroll
    for (int i = 0; i < 8; i++) {
        const int row = bm + ty * 8 + i;
        #pragma unroll
        for (int j = 0; j < 8; j += 4) {
            const int col = bn + tx * 8 + j;
            float4 v;
            v.x = acc[i][j + 0] + bias[col + 0];
            v.y = acc[i][j + 1] + bias[col + 1];
            v.z = acc[i][j + 2] + bias[col + 2];
            v.w = acc[i][j + 3] + bias[col + 3];
            if (relu) {
                v.x = fmaxf(v.x, 0.f); v.y = fmaxf(v.y, 0.f);
                v.z = fmaxf(v.z, 0.f); v.w = fmaxf(v.w, 0.f);
            }
            v.x *= scale; v.y *= scale; v.z *= scale; v.w *= scale;
            if (res) {
                const float4 r = *reinterpret_cast<const float4*>(&res[(size_t)row * N + col]);
                v.x += r.x; v.y += r.y; v.z += r.z; v.w += r.w;
            }
            *reinterpret_cast<float4*>(&C[(size_t)row * N + col]) = v;
        }
    }
}

// ---------------- scores[bh, s, t] = sum_d q[b,s,h,d] * k[b,t,h,d]  (+mask) ----------------
// grid: (NS/64, NS/64, NB*NH), 256 threads, 64x64 tile, K = 64
__global__ __launch_bounds__(256)
void score_kernel(const float* __restrict__ q, const float* __restrict__ k,
                  const unsigned char* __restrict__ mask, float* __restrict__ sc) {
    __shared__ float Qs[NDH][64 + 4];   // [k][row]
    __shared__ float Ks[NDH][64 + 4];   // [k][col]
    const int bh = blockIdx.z;
    const int b = bh >> 4, h = bh & 15;
    const int s0 = blockIdx.y * 64, t0 = blockIdx.x * 64;
    const int tid = threadIdx.x;
    const int tx = tid & 15, ty = tid >> 4;

    const float* qb = q + ((size_t)b * NS) * ND + h * NDH;
    const float* kb = k + ((size_t)b * NS) * ND + h * NDH;

    #pragma unroll
    for (int i = 0; i < 4; i++) {
        const int f = tid + i * 256;           // 1024 float4 per tile
        const int row = f >> 4, kc = (f & 15) << 2;
        const float4 a = *reinterpret_cast<const float4*>(&qb[(size_t)(s0 + row) * ND + kc]);
        Qs[kc + 0][row] = a.x; Qs[kc + 1][row] = a.y;
        Qs[kc + 2][row] = a.z; Qs[kc + 3][row] = a.w;
        const float4 c = *reinterpret_cast<const float4*>(&kb[(size_t)(t0 + row) * ND + kc]);
        Ks[kc + 0][row] = c.x; Ks[kc + 1][row] = c.y;
        Ks[kc + 2][row] = c.z; Ks[kc + 3][row] = c.w;
    }
    __syncthreads();

    float acc[4][4];
    #pragma unroll
    for (int i = 0; i < 4; i++)
        #pragma unroll
        for (int j = 0; j < 4; j++) acc[i][j] = 0.f;

    #pragma unroll 8
    for (int kk = 0; kk < NDH; kk++) {
        float ar[4], br[4];
        *reinterpret_cast<float4*>(ar) = *reinterpret_cast<const float4*>(&Qs[kk][ty * 4]);
        *reinterpret_cast<float4*>(br) = *reinterpret_cast<const float4*>(&Ks[kk][tx * 4]);
        #pragma unroll
        for (int i = 0; i < 4; i++)
            #pragma unroll
            for (int j = 0; j < 4; j++)
                acc[i][j] = fmaf(ar[i], br[j], acc[i][j]);
    }

    float* out = sc + (size_t)bh * NS * NS;
    #pragma unroll
    for (int i = 0; i < 4; i++) {
        const int s = s0 + ty * 4 + i;
        const int t = t0 + tx * 4;
        const uchar4 m4 = *reinterpret_cast<const uchar4*>(
            &mask[((size_t)b * NS + s) * NS + t]);
        float4 v;
        v.x = m4.x ? -1e18f : acc[i][0];
        v.y = m4.y ? -1e18f : acc[i][1];
        v.z = m4.z ? -1e18f : acc[i][2];
        v.w = m4.w ? -1e18f : acc[i][3];
        *reinterpret_cast<float4*>(&out[(size_t)s * NS + t]) = v;
    }
}

// ---------------- row softmax over 2048, one block per row ----------------
__global__ void softmax_kernel(float* __restrict__ sc) {
    __shared__ float red[8];
    const size_t row = blockIdx.x;
    float4* p = reinterpret_cast<float4*>(sc + row * NS);
    const int t = threadIdx.x;
    float4 v0 = p[t], v1 = p[t + 256];

    float m = fmaxf(fmaxf(fmaxf(v0.x, v0.y), fmaxf(v0.z, v0.w)),
                    fmaxf(fmaxf(v1.x, v1.y), fmaxf(v1.z, v1.w)));
    #pragma unroll
    for (int o = 16; o; o >>= 1) m = fmaxf(m, __shfl_xor_sync(0xffffffffu, m, o));
    if ((t & 31) == 0) red[t >> 5] = m;
    __syncthreads();
    float rm = red[0];
    #pragma unroll
    for (int i = 1; i < 8; i++) rm = fmaxf(rm, red[i]);
    __syncthreads();

    v0.x = __expf(v0.x - rm); v0.y = __expf(v0.y - rm);
    v0.z = __expf(v0.z - rm); v0.w = __expf(v0.w - rm);
    v1.x = __expf(v1.x - rm); v1.y = __expf(v1.y - rm);
    v1.z = __expf(v1.z - rm); v1.w = __expf(v1.w - rm);

    float s = v0.x + v0.y + v0.z + v0.w + v1.x + v1.y + v1.z + v1.w;
    #pragma unroll
    for (int o = 16; o; o >>= 1) s += __shfl_xor_sync(0xffffffffu, s, o);
    if ((t & 31) == 0) red[t >> 5] = s;
    __syncthreads();
    float tot = 0.f;
    #pragma unroll
    for (int i = 0; i < 8; i++) tot += red[i];
    const float inv = 1.0f / tot;

    v0.x *= inv; v0.y *= inv; v0.z *= inv; v0.w *= inv;
    v1.x *= inv; v1.y *= inv; v1.z *= inv; v1.w *= inv;
    p[t] = v0; p[t + 256] = v1;
}

// ---------------- ctx[b, s, h*64+c] = sum_t attn[bh, s, t] * v[b,t,h,c] ----------------
// grid: (NS/64, NB*NH), 256 threads, 64x64 output tile, K = 2048 in BK=32 steps
__global__ __launch_bounds__(256)
void ctx_kernel(const float* __restrict__ attn, const float* __restrict__ v,
                float* __restrict__ ctx) {
    __shared__ float As[32][64 + 4];   // [k][row] (attn tile transposed)
    __shared__ float Vs[32][64 + 4];   // [k][col]
    const int bh = blockIdx.y;
    const int b = bh >> 4, h = bh & 15;
    const int s0 = blockIdx.x * 64;
    const int tid = threadIdx.x;
    const int tx = tid & 15, ty = tid >> 4;

    const float* Ab = attn + (size_t)bh * NS * NS;
    const float* Vb = v + ((size_t)b * NS) * ND + h * NDH;

    float acc[4][4];
    #pragma unroll
    for (int i = 0; i < 4; i++)
        #pragma unroll
        for (int j = 0; j < 4; j++) acc[i][j] = 0.f;

    for (int k0 = 0; k0 < NS; k0 += 32) {
        #pragma unroll
        for (int i = 0; i < 2; i++) {
            const int f = tid + i * 256;          // 512 float4 per tile
            const int ar = f >> 3, ac = (f & 7) << 2;   // 64 rows x 32 k
            const float4 a = *reinterpret_cast<const float4*>(
                &Ab[(size_t)(s0 + ar) * NS + k0 + ac]);
            As[ac + 0][ar] = a.x; As[ac + 1][ar] = a.y;
            As[ac + 2][ar] = a.z; As[ac + 3][ar] = a.w;
            const int vr = f >> 4, vc = (f & 15) << 2;  // 32 rows x 64 cols
            *reinterpret_cast<float4*>(&Vs[vr][vc]) =
                *reinterpret_cast<const float4*>(&Vb[(size_t)(k0 + vr) * ND + vc]);
        }
        __syncthreads();
        #pragma unroll
        for (int k = 0; k < 32; k++) {
            float ar[4], br[4];
            *reinterpret_cast<float4*>(ar) = *reinterpret_cast<const float4*>(&As[k][ty * 4]);
            *reinterpret_cast<float4*>(br) = *reinterpret_cast<const float4*>(&Vs[k][tx * 4]);
            #pragma unroll
            for (int i = 0; i < 4; i++)
                #pragma unroll
                for (int j = 0; j < 4; j++)
                    acc[i][j] = fmaf(ar[i], br[j], acc[i][j]);
        }
        __syncthreads();
    }

    #pragma unroll
    for (int i = 0; i < 4; i++) {
        const int s = s0 + ty * 4 + i;
        float4 o;
        o.x = acc[i][0]; o.y = acc[i][1]; o.z = acc[i][2]; o.w = acc[i][3];
        *reinterpret_cast<float4*>(
            &ctx[((size_t)b * NS + s) * ND + h * NDH + tx * 4]) = o;
    }
}

// ---------------- host launch ----------------
extern "C" void kernel_launch(void* const* d_in, const int* in_sizes, int n_in,
                              void* d_out, int out_size) {
    const float* x   = (const float*)d_in[0];
    const unsigned char* mask = (const unsigned char*)d_in[1];
    const float* Wq  = (const float*)d_in[2];
    const float* bq  = (const float*)d_in[3];
    const float* Wk  = (const float*)d_in[4];
    const float* bk  = (const float*)d_in[5];
    const float* Wv  = (const float*)d_in[6];
    const float* bv  = (const float*)d_in[7];
    const float* Wo  = (const float*)d_in[8];
    const float* bo  = (const float*)d_in[9];
    const float* ln1g = (const float*)d_in[10];
    const float* ln1b = (const float*)d_in[11];
    const float* ln2g = (const float*)d_in[12];
    const float* ln2b = (const float*)d_in[13];
    const float* W1  = (const float*)d_in[14];
    const float* b1  = (const float*)d_in[15];
    const float* W2  = (const float*)d_in[16];
    const float* b2  = (const float*)d_in[17];
    float* out = (float*)d_out;

    float *h, *q, *k, *v, *ctx, *ffn, *sc;
    cudaGetSymbolAddress((void**)&h,   g_h);
    cudaGetSymbolAddress((void**)&q,   g_q);
    cudaGetSymbolAddress((void**)&k,   g_k);
    cudaGetSymbolAddress((void**)&v,   g_v);
    cudaGetSymbolAddress((void**)&ctx, g_ctx);
    cudaGetSymbolAddress((void**)&ffn, g_ffn);
    cudaGetSymbolAddress((void**)&sc,  g_sc);

    const float qscale = 0.125f;   // 1/sqrt(64)

    // 1. LN1
    ln_kernel<<<NM, 256>>>(x, ln1g, ln1b, h);
    // 2-4. Q,K,V projections
    sgemm_kernel<<<dim3(ND/128, NM/128), 256>>>(NM, ND, ND, h, Wq, bq, nullptr, q, qscale, 0);
    sgemm_kernel<<<dim3(ND/128, NM/128), 256>>>(NM, ND, ND, h, Wk, bk, nullptr, k, 1.0f, 0);
    sgemm_kernel<<<dim3(ND/128, NM/128), 256>>>(NM, ND, ND, h, Wv, bv, nullptr, v, 1.0f, 0);
    // 5. scores (+mask)
    score_kernel<<<dim3(NS/64, NS/64, NB*NH), 256>>>(q, k, mask, sc);
    // 6. softmax
    softmax_kernel<<<NB*NH*NS, 256>>>(sc);
    // 7. ctx = attn @ V  (written directly in [B,S,D] layout)
    ctx_kernel<<<dim3(NS/64, NB*NH), 256>>>(sc, v, ctx);
    // 8. x1 = x + ctx @ Wo + bo   -> d_out
    sgemm_kernel<<<dim3(ND/128, NM/128), 256>>>(NM, ND, ND, ctx, Wo, bo, x, out, 1.0f, 0);
    // 9. LN2
    ln_kernel<<<NM, 256>>>(out, ln2g, ln2b, h);
    // 10. ffn = relu(h @ W1 + b1)
    sgemm_kernel<<<dim3(NF/128, NM/128), 256>>>(NM, NF, ND, h, W1, b1, nullptr, ffn, 1.0f, 1);
    // 11. out = x1 + ffn @ W2 + b2
    sgemm_kernel<<<dim3(ND/128, NM/128), 256>>>(NM, ND, NF, ffn, W2, b2, out, out, 1.0f, 0);
}